// round 1
// baseline (speedup 1.0000x reference)
#include <cuda_runtime.h>
#include <cstddef>

// ---------------- scratch (no allocations allowed -> __device__ globals) ----
#define MAX_EDGES 2000000
#define MAX_NODES 100000
#define BUF_STRIDE 160

__device__ float g_bufA[(size_t)MAX_EDGES * BUF_STRIDE];
__device__ float g_bufB[(size_t)MAX_EDGES * BUF_STRIDE];
__device__ float g_eprime[(size_t)MAX_NODES * 64];

// ---------------- gather: build R_prime [M,16] (cols: xs0..3, os0..1, xt0..3, ot0..1, t, 0,0,0)
__global__ void gather_kernel(const float* __restrict__ x,
                              const float* __restrict__ ofx,
                              const int* __restrict__ src,
                              const int* __restrict__ tgt,
                              const float* __restrict__ t,
                              float* __restrict__ out, int M)
{
    int e = blockIdx.x * blockDim.x + threadIdx.x;
    if (e >= M) return;
    int s = src[e], g = tgt[e];
    float4 xs = *(const float4*)(x + (size_t)4 * s);
    float2 os = *(const float2*)(ofx + (size_t)2 * s);
    float4 xt = *(const float4*)(x + (size_t)4 * g);
    float2 ot = *(const float2*)(ofx + (size_t)2 * g);
    float tv = t[0];
    float4* o = (float4*)(out + (size_t)e * 16);
    o[0] = xs;
    o[1] = make_float4(os.x, os.y, xt.x, xt.y);
    o[2] = make_float4(xt.z, xt.w, ot.x, ot.y);
    o[3] = make_float4(tv, 0.f, 0.f, 0.f);
}

// ---------------- zero E' ------------------------------------------------
__global__ void zero_kernel(float* __restrict__ p, int n)
{
    int i = blockIdx.x * blockDim.x + threadIdx.x;
    if (i < n) p[i] = 0.f;
}

// ---------------- scatter-add: E[M,50] (stride 160) -> E'[N,64] -----------
__global__ void scatter_kernel(const float* __restrict__ E,
                               const int* __restrict__ tgt,
                               float* __restrict__ ep, int M)
{
    int idx = blockIdx.x * blockDim.x + threadIdx.x;
    int e = idx >> 5;
    if (e >= M) return;
    int lane = idx & 31;
    int tg = __ldg(tgt + e);
    const float* Er = E + (size_t)e * BUF_STRIDE;
    float* dst = ep + (size_t)tg * 64;
    atomicAdd(dst + lane, Er[lane]);
    if (lane < 18) atomicAdd(dst + lane + 32, Er[lane + 32]);
}

// ---------------- generic fp32 GEMM + bias + optional ReLU ----------------
// C[M,dout] = act(A[M,din] * W[din,dout] + b)
// Persistent grid; per block: full padded W in smem + 64-row A tile.
// 256 threads; warp w owns rows w*8..w*8+7; lane owns cols lane+32*s, s<NS.
template <int NS>
__global__ __launch_bounds__(256)
void gemm_kernel(const float* __restrict__ A, int lda,
                 const float* __restrict__ W, const float* __restrict__ B,
                 float* __restrict__ C, int ldc,
                 int M, int din, int dout, int dinp, int relu, int padstore)
{
    constexpr int PN = NS * 32;
    extern __shared__ float smem[];
    float* Ws = smem;                 // [dinp][PN], zero-padded
    float* Bs = Ws + dinp * PN;       // [PN]
    float* As = Bs + PN;              // [64][dinp]
    const int tid = threadIdx.x;
    const int din4 = (din + 3) & ~3;

    for (int idx = tid; idx < dinp * PN; idx += 256) {
        int k = idx / PN;
        int j = idx - k * PN;
        Ws[idx] = (k < din && j < dout) ? W[(size_t)k * dout + j] : 0.f;
    }
    for (int j = tid; j < PN; j += 256)
        Bs[j] = (j < dout) ? B[j] : 0.f;
    __syncthreads();

    const int lane = tid & 31;
    const int wrp  = tid >> 5;
    const int kv4  = dinp >> 2;
    const int ntiles = (M + 63) >> 6;

    for (int tile = blockIdx.x; tile < ntiles; tile += gridDim.x) {
        const int row0 = tile << 6;
        // load A tile (vectorized, zero-fill OOB rows)
        for (int idx = tid; idx < (kv4 << 6); idx += 256) {
            int m  = idx / kv4;
            int kv = idx - m * kv4;
            int row = row0 + m;
            float4 v = make_float4(0.f, 0.f, 0.f, 0.f);
            if (row < M)
                v = *(const float4*)(A + (size_t)row * lda + (kv << 2));
            *(float4*)(As + m * dinp + (kv << 2)) = v;
        }
        __syncthreads();

        float acc[8][NS];
#pragma unroll
        for (int r = 0; r < 8; r++)
#pragma unroll
            for (int s = 0; s < NS; s++) acc[r][s] = 0.f;

        const float* AsB = As + (wrp << 3) * dinp;
        for (int k = 0; k < din4; k += 4) {
            float wv[4][NS];
#pragma unroll
            for (int kk = 0; kk < 4; kk++)
#pragma unroll
                for (int s = 0; s < NS; s++)
                    wv[kk][s] = Ws[(k + kk) * PN + lane + (s << 5)];
#pragma unroll
            for (int r = 0; r < 8; r++) {
                float4 a = *(const float4*)(AsB + r * dinp + k);
#pragma unroll
                for (int s = 0; s < NS; s++) {
                    acc[r][s] = fmaf(a.x, wv[0][s], acc[r][s]);
                    acc[r][s] = fmaf(a.y, wv[1][s], acc[r][s]);
                    acc[r][s] = fmaf(a.z, wv[2][s], acc[r][s]);
                    acc[r][s] = fmaf(a.w, wv[3][s], acc[r][s]);
                }
            }
        }

#pragma unroll
        for (int r = 0; r < 8; r++) {
            int row = row0 + (wrp << 3) + r;
            if (row < M) {
#pragma unroll
                for (int s = 0; s < NS; s++) {
                    int j = lane + (s << 5);
                    float v = acc[r][s] + Bs[j];
                    if (relu) v = fmaxf(v, 0.f);
                    if (padstore || j < dout)
                        C[(size_t)row * ldc + j] = v;
                }
            }
        }
        __syncthreads();
    }
}

// ---------------- host ----------------------------------------------------
static inline size_t smbytes(int dinp, int PN)
{
    return (size_t)(dinp * PN + PN + 64 * dinp) * sizeof(float);
}

extern "C" void kernel_launch(void* const* d_in, const int* in_sizes, int n_in,
                              void* d_out, int out_size)
{
    const float* t    = (const float*)d_in[0];
    const float* x    = (const float*)d_in[1];
    const float* ofx  = (const float*)d_in[2];
    const int*   src  = (const int*)d_in[3];
    const int*   tgt  = (const int*)d_in[4];
    const float* RW0  = (const float*)d_in[5];
    const float* Rb0  = (const float*)d_in[6];
    const float* RW1  = (const float*)d_in[7];
    const float* Rb1  = (const float*)d_in[8];
    const float* RW2  = (const float*)d_in[9];
    const float* Rb2  = (const float*)d_in[10];
    const float* RW3  = (const float*)d_in[11];
    const float* Rb3  = (const float*)d_in[12];
    const float* RW4  = (const float*)d_in[13];
    const float* Rb4  = (const float*)d_in[14];
    const float* OW0  = (const float*)d_in[15];
    const float* Ob0  = (const float*)d_in[16];
    const float* OW1  = (const float*)d_in[17];
    const float* Ob1  = (const float*)d_in[18];
    float* out = (float*)d_out;

    const int M = in_sizes[3];      // n edges
    const int N = in_sizes[1] / 4;  // n nodes

    float *bufA, *bufB, *ep;
    cudaGetSymbolAddress((void**)&bufA, g_bufA);
    cudaGetSymbolAddress((void**)&bufB, g_bufB);
    cudaGetSymbolAddress((void**)&ep,   g_eprime);

    int nsm = 148;
    cudaDeviceGetAttribute(&nsm, cudaDevAttrMultiProcessorCount, 0);

    cudaFuncSetAttribute(gemm_kernel<5>, cudaFuncAttributeMaxDynamicSharedMemorySize, 160 * 1024);
    cudaFuncSetAttribute(gemm_kernel<4>, cudaFuncAttributeMaxDynamicSharedMemorySize, 160 * 1024);
    cudaFuncSetAttribute(gemm_kernel<2>, cudaFuncAttributeMaxDynamicSharedMemorySize, 160 * 1024);
    cudaFuncSetAttribute(gemm_kernel<1>, cudaFuncAttributeMaxDynamicSharedMemorySize, 160 * 1024);

    // zero E'
    zero_kernel<<<(N * 64 + 255) / 256, 256>>>(ep, N * 64);
    // R' gather into bufA (stride 16, zero-padded cols 13..15)
    gather_kernel<<<(M + 255) / 256, 256>>>(x, ofx, src, tgt, t, bufA, M);

    // edge MLP
    gemm_kernel<5><<<nsm, 256, smbytes(16, 160)>>>(bufA, 16,  RW0, Rb0, bufB, 160, M, 13,  150, 16,  1, 1);
    gemm_kernel<5><<<nsm, 256, smbytes(160, 160)>>>(bufB, 160, RW1, Rb1, bufA, 160, M, 150, 150, 160, 1, 1);
    gemm_kernel<5><<<nsm, 256, smbytes(160, 160)>>>(bufA, 160, RW2, Rb2, bufB, 160, M, 150, 150, 160, 1, 1);
    gemm_kernel<5><<<nsm, 256, smbytes(160, 160)>>>(bufB, 160, RW3, Rb3, bufA, 160, M, 150, 150, 160, 1, 1);
    gemm_kernel<2><<<nsm, 256, smbytes(160, 64)>>>(bufA, 160, RW4, Rb4, bufB, 160, M, 150, 50,  160, 0, 1);

    // segment-sum (scatter add): E (bufB, stride 160, cols 0..49) -> E' [N,64]
    scatter_kernel<<<(M * 32 + 255) / 256, 256>>>(bufB, tgt, ep, M);

    // node MLP
    gemm_kernel<4><<<nsm, 256, smbytes(64, 128)>>>(ep,   64,  OW0, Ob0, bufA, 128, N, 50,  100, 64,  1, 1);
    gemm_kernel<1><<<nsm, 256, smbytes(128, 32)>>>(bufA, 128, OW1, Ob1, out,  4,   N, 100, 4,   128, 0, 0);
}

// round 2
// speedup vs baseline: 1.4184x; 1.4184x over previous
#include <cuda_runtime.h>
#include <cstddef>

// ---------------- scratch (no allocations allowed -> __device__ globals) ----
#define MAX_EDGES 2000000
#define MAX_NODES 100000

__device__ float g_bufA[(size_t)MAX_EDGES * 160];
__device__ float g_bufB[(size_t)MAX_EDGES * 160];
__device__ float g_eprime[(size_t)MAX_NODES * 64];

// ---------------- gather: build R_prime [M,16] ----------------------------
__global__ void gather_kernel(const float* __restrict__ x,
                              const float* __restrict__ ofx,
                              const int* __restrict__ src,
                              const int* __restrict__ tgt,
                              const float* __restrict__ t,
                              float* __restrict__ out, int M)
{
    int e = blockIdx.x * blockDim.x + threadIdx.x;
    if (e >= M) return;
    int s = src[e], g = tgt[e];
    float4 xs = *(const float4*)(x + (size_t)4 * s);
    float2 os = *(const float2*)(ofx + (size_t)2 * s);
    float4 xt = *(const float4*)(x + (size_t)4 * g);
    float2 ot = *(const float2*)(ofx + (size_t)2 * g);
    float tv = t[0];
    float4* o = (float4*)(out + (size_t)e * 16);
    o[0] = xs;
    o[1] = make_float4(os.x, os.y, xt.x, xt.y);
    o[2] = make_float4(xt.z, xt.w, ot.x, ot.y);
    o[3] = make_float4(tv, 0.f, 0.f, 0.f);
}

// ---------------- zero E' --------------------------------------------------
__global__ void zero_kernel(float* __restrict__ p, int n)
{
    int i = blockIdx.x * blockDim.x + threadIdx.x;
    if (i < n) p[i] = 0.f;
}

// ---------------- scatter-add: E[M,50] (stride 64) -> E'[N,64] -------------
__global__ void scatter_kernel(const float* __restrict__ E,
                               const int* __restrict__ tgt,
                               float* __restrict__ ep, int M)
{
    int idx = blockIdx.x * blockDim.x + threadIdx.x;
    int e = idx >> 5;
    if (e >= M) return;
    int lane = idx & 31;
    int tg = __ldg(tgt + e);
    const float* Er = E + (size_t)e * 64;
    float* dst = ep + (size_t)tg * 64;
    atomicAdd(dst + lane, Er[lane]);
    if (lane < 18) atomicAdd(dst + lane + 32, Er[lane + 32]);
}

// ---------------- fp32 GEMM + bias + optional ReLU -------------------------
// C[M,dout-ish] = act(A[M,din] * W[din,dout] + b)
// Weights fully resident in smem (zero-padded to [din4][PN]). NO smem A tile,
// NO barriers in the main loop: each warp owns independent 8-row strips and
// streams A rows from gmem with LDG.128. 256 thr, 2 CTAs/SM -> 4 warps/SMSP.
template <int NS>
__global__ __launch_bounds__(256, 2)
void gemm_kernel(const float* __restrict__ A, int lda,
                 const float* __restrict__ W, const float* __restrict__ B,
                 float* __restrict__ C, int ldc,
                 int M, int din, int dout, int relu, int padstore)
{
    constexpr int PN = NS * 32;
    extern __shared__ float smem[];
    float* Ws = smem;                 // [din4][PN], zero-padded
    float* Bs = Ws + ((din + 3) & ~3) * PN;   // [PN]
    const int tid = threadIdx.x;
    const int din4 = (din + 3) & ~3;

    for (int idx = tid; idx < din4 * PN; idx += 256) {
        int k = idx / PN;
        int j = idx - k * PN;
        Ws[idx] = (k < din && j < dout) ? W[(size_t)k * dout + j] : 0.f;
    }
    for (int j = tid; j < PN; j += 256)
        Bs[j] = (j < dout) ? B[j] : 0.f;
    __syncthreads();

    const int lane = tid & 31;
    const int gwarp = blockIdx.x * 8 + (tid >> 5);
    const int nwarp = gridDim.x * 8;
    const int nstrips = (M + 7) >> 3;

    for (int sidx = gwarp; sidx < nstrips; sidx += nwarp) {
        const int row0 = sidx << 3;

        const float* ap[8];
#pragma unroll
        for (int r = 0; r < 8; r++) {
            int rr = row0 + r;
            if (rr > M - 1) rr = M - 1;     // clamp (results discarded)
            ap[r] = A + (size_t)rr * lda;
        }

        float acc[8][NS];
#pragma unroll
        for (int r = 0; r < 8; r++)
#pragma unroll
            for (int s = 0; s < NS; s++) acc[r][s] = 0.f;

#pragma unroll 2
        for (int k = 0; k < din4; k += 4) {
            float4 a[8];
#pragma unroll
            for (int r = 0; r < 8; r++)
                a[r] = *(const float4*)(ap[r] + k);

#pragma unroll
            for (int kk = 0; kk < 4; kk++) {
                float wv[NS];
#pragma unroll
                for (int s = 0; s < NS; s++)
                    wv[s] = Ws[(k + kk) * PN + lane + (s << 5)];
#pragma unroll
                for (int r = 0; r < 8; r++) {
                    float av = (kk == 0) ? a[r].x : (kk == 1) ? a[r].y
                             : (kk == 2) ? a[r].z : a[r].w;
#pragma unroll
                    for (int s = 0; s < NS; s++)
                        acc[r][s] = fmaf(av, wv[s], acc[r][s]);
                }
            }
        }

#pragma unroll
        for (int r = 0; r < 8; r++) {
            int row = row0 + r;
            if (row < M) {
#pragma unroll
                for (int s = 0; s < NS; s++) {
                    int j = lane + (s << 5);
                    float v = acc[r][s] + Bs[j];
                    if (relu) v = fmaxf(v, 0.f);
                    if (padstore || j < dout)
                        C[(size_t)row * ldc + j] = v;
                }
            }
        }
    }
}

// ---------------- host ------------------------------------------------------
static inline size_t smbytes(int din, int PN)
{
    int din4 = (din + 3) & ~3;
    return (size_t)(din4 * PN + PN) * sizeof(float);
}

extern "C" void kernel_launch(void* const* d_in, const int* in_sizes, int n_in,
                              void* d_out, int out_size)
{
    const float* t    = (const float*)d_in[0];
    const float* x    = (const float*)d_in[1];
    const float* ofx  = (const float*)d_in[2];
    const int*   src  = (const int*)d_in[3];
    const int*   tgt  = (const int*)d_in[4];
    const float* RW0  = (const float*)d_in[5];
    const float* Rb0  = (const float*)d_in[6];
    const float* RW1  = (const float*)d_in[7];
    const float* Rb1  = (const float*)d_in[8];
    const float* RW2  = (const float*)d_in[9];
    const float* Rb2  = (const float*)d_in[10];
    const float* RW3  = (const float*)d_in[11];
    const float* Rb3  = (const float*)d_in[12];
    const float* RW4  = (const float*)d_in[13];
    const float* Rb4  = (const float*)d_in[14];
    const float* OW0  = (const float*)d_in[15];
    const float* Ob0  = (const float*)d_in[16];
    const float* OW1  = (const float*)d_in[17];
    const float* Ob1  = (const float*)d_in[18];
    float* out = (float*)d_out;

    const int M = in_sizes[3];      // n edges
    const int N = in_sizes[1] / 4;  // n nodes

    float *bufA, *bufB, *ep;
    cudaGetSymbolAddress((void**)&bufA, g_bufA);
    cudaGetSymbolAddress((void**)&bufB, g_bufB);
    cudaGetSymbolAddress((void**)&ep,   g_eprime);

    int nsm = 148;
    cudaDeviceGetAttribute(&nsm, cudaDevAttrMultiProcessorCount, 0);
    const int nblk = 2 * nsm;

    cudaFuncSetAttribute(gemm_kernel<5>, cudaFuncAttributeMaxDynamicSharedMemorySize, 112 * 1024);
    cudaFuncSetAttribute(gemm_kernel<4>, cudaFuncAttributeMaxDynamicSharedMemorySize, 112 * 1024);
    cudaFuncSetAttribute(gemm_kernel<2>, cudaFuncAttributeMaxDynamicSharedMemorySize, 112 * 1024);
    cudaFuncSetAttribute(gemm_kernel<1>, cudaFuncAttributeMaxDynamicSharedMemorySize, 112 * 1024);

    // zero E'
    zero_kernel<<<(N * 64 + 255) / 256, 256>>>(ep, N * 64);
    // R' gather into bufA (stride 16, zero-padded cols 13..15)
    gather_kernel<<<(M + 255) / 256, 256>>>(x, ofx, src, tgt, t, bufA, M);

    // edge MLP (intermediates stride 160, padded cols written as exact zeros)
    gemm_kernel<5><<<nblk, 256, smbytes(13, 160)>>>(bufA, 16,  RW0, Rb0, bufB, 160, M, 13,  150, 1, 1);
    gemm_kernel<5><<<nblk, 256, smbytes(150, 160)>>>(bufB, 160, RW1, Rb1, bufA, 160, M, 150, 150, 1, 1);
    gemm_kernel<5><<<nblk, 256, smbytes(150, 160)>>>(bufA, 160, RW2, Rb2, bufB, 160, M, 150, 150, 1, 1);
    gemm_kernel<5><<<nblk, 256, smbytes(150, 160)>>>(bufB, 160, RW3, Rb3, bufA, 160, M, 150, 150, 1, 1);
    // L5: compact output (stride 64), only real 50 cols written
    gemm_kernel<2><<<nblk, 256, smbytes(150, 64)>>>(bufA, 160, RW4, Rb4, bufB, 64, M, 150, 50, 0, 0);

    // segment-sum (scatter add): E (bufB, stride 64, cols 0..49) -> E' [N,64]
    scatter_kernel<<<(M * 32 + 255) / 256, 256>>>(bufB, tgt, ep, M);

    // node MLP
    gemm_kernel<4><<<nblk, 256, smbytes(50, 128)>>>(ep,   64,  OW0, Ob0, bufA, 128, N, 50,  100, 1, 1);
    gemm_kernel<1><<<nblk, 256, smbytes(100, 32)>>>(bufA, 128, OW1, Ob1, out,  4,   N, 100, 4,   0, 0);
}